// round 16
// baseline (speedup 1.0000x reference)
#include <cuda_runtime.h>
#include <cuda_fp16.h>

// Dims fixed by the reference: x is (B=8, T=2048, F=128) float32.
#define BB 8
#define TT 2048
#define FF 128
#define NN (BB * TT * FF)           // 2,097,152
#define SB (TT * FF)                // 262144
#define ST (FF)                     // 128

#define TAU_F (1.0f / 6.0f)
#define NFUSED 28                   // updates #2..#29 (update #1 is k_first)

#define TTILE 4                     // output T-rows per block (grid = 512)
#define NTFUSED 512                 // 16 warps: (b, half) ownership
#define NTHREADS 256                // k_first / k_final

// Ping-pong dual buffers + fp16 image copy. No runtime allocation.
__device__ __half g_pa0[NN], g_pa1[NN], g_pa2[NN];
__device__ __half g_pb0[NN], g_pb1[NN], g_pb2[NN];
__device__ __half g_imgh[NN];

// ---------------- fp32 helpers (k_first / k_final only) --------------------
__device__ __forceinline__ float4 ld4(const float* __restrict__ p, int idx) {
    return *reinterpret_cast<const float4*>(p + idx);
}
__device__ __forceinline__ void st4(float* __restrict__ p, int idx, float4 v) {
    *reinterpret_cast<float4*>(p + idx) = v;
}
__device__ __forceinline__ float4 u2tof4(uint2 u) {
    __half2 h0 = *reinterpret_cast<__half2*>(&u.x);
    __half2 h1 = *reinterpret_cast<__half2*>(&u.y);
    float2 f0 = __half22float2(h0);
    float2 f1 = __half22float2(h1);
    return make_float4(f0.x, f0.y, f1.x, f1.y);
}
__device__ __forceinline__ uint2 f4tou2(float4 v) {
    __half2 h0 = __floats2half2_rn(v.x, v.y);
    __half2 h1 = __floats2half2_rn(v.z, v.w);
    uint2 u;
    u.x = *reinterpret_cast<unsigned*>(&h0);
    u.y = *reinterpret_cast<unsigned*>(&h1);
    return u;
}
__device__ __forceinline__ float4 ldh4(const __half* __restrict__ p, int idx) {
    return u2tof4(*reinterpret_cast<const uint2*>(p + idx));
}
__device__ __forceinline__ void sth4(__half* __restrict__ p, int idx, float4 v) {
    *reinterpret_cast<uint2*>(p + idx) = f4tou2(v);
}
__device__ __forceinline__ float4 f4sub(float4 a, float4 b) {
    return make_float4(a.x - b.x, a.y - b.y, a.z - b.z, a.w - b.w);
}
__device__ __forceinline__ float4 f4add(float4 a, float4 b) {
    return make_float4(a.x + b.x, a.y + b.y, a.z + b.z, a.w + b.w);
}

// ---------------- half2 helpers --------------------------------------------
struct H4 { __half2 lo, hi; };
__device__ __forceinline__ H4 ldH4(const __half* __restrict__ p, int idx) {
    uint2 u = *reinterpret_cast<const uint2*>(p + idx);
    H4 r;
    r.lo = *reinterpret_cast<__half2*>(&u.x);
    r.hi = *reinterpret_cast<__half2*>(&u.y);
    return r;
}
__device__ __forceinline__ void stH4(__half* __restrict__ p, int idx, H4 v) {
    uint2 u;
    u.x = *reinterpret_cast<unsigned*>(&v.lo);
    u.y = *reinterpret_cast<unsigned*>(&v.hi);
    *reinterpret_cast<uint2*>(p + idx) = u;
}
__device__ __forceinline__ unsigned h2u(__half2 h) {
    return *reinterpret_cast<unsigned*>(&h);
}
__device__ __forceinline__ __half2 u2h(unsigned u) {
    return *reinterpret_cast<__half2*>(&u);
}

// ---------------------------------------------------------------------------
// k_first: p = 0  =>  out = img, g = grad(img). Writes pA (fp16) + img_h.
// ---------------------------------------------------------------------------
__global__ __launch_bounds__(NTHREADS)
void k_first(const float* __restrict__ img, const float* __restrict__ lam) {
    int tid = blockIdx.x * blockDim.x + threadIdx.x;   // float4 index
    if (tid >= NN / 4) return;
    int lane = tid & 31;
    int t = (tid >> 5) & (TT - 1);
    int b = tid >> 16;
    int idx = tid * 4;

    float4 o = ld4(img, idx);
    *reinterpret_cast<uint2*>(g_imgh + idx) = f4tou2(o);

    float4 gb = make_float4(0, 0, 0, 0), gt = make_float4(0, 0, 0, 0), gf;
    if (b < BB - 1) gb = f4sub(ld4(img, idx + SB), o);
    if (t < TT - 1) gt = f4sub(ld4(img, idx + ST), o);
    float nx = __shfl_down_sync(0xffffffffu, o.x, 1);
    gf.x = o.y - o.x; gf.y = o.z - o.y; gf.z = o.w - o.z;
    gf.w = (lane < 31) ? (nx - o.w) : 0.0f;

    float tw = TAU_F / lam[0];
    float4 r0, r1, r2;
#define FIRST_UPD(c)                                                     \
    { float n = sqrtf(gb.c * gb.c + gt.c * gt.c + gf.c * gf.c);          \
      float inv = __fdividef(1.0f, n * tw + 1.0f);                       \
      r0.c = (-TAU_F * gb.c) * inv;                                      \
      r1.c = (-TAU_F * gt.c) * inv;                                      \
      r2.c = (-TAU_F * gf.c) * inv; }
    FIRST_UPD(x) FIRST_UPD(y) FIRST_UPD(z) FIRST_UPD(w)
#undef FIRST_UPD
    sth4(g_pa0, idx, r0);
    sth4(g_pa1, idx, r1);
    sth4(g_pa2, idx, r2);
}

// Compute out = img + div(p) for one (b, t) row (half2 x2 per thread).
// a1c carries this row's a1 out (for the next row's t-1 term).
__device__ __forceinline__ void out_row(const __half* __restrict__ q0,
                                        const __half* __restrict__ q1,
                                        const __half* __restrict__ q2,
                                        int b, int t, int lane, bool use_carry,
                                        __half2& a1clo, __half2& a1chi,
                                        __half2& dlo, __half2& dhi) {
    const __half zeroh = __float2half(0.0f);
    int idx = b * SB + t * ST + lane * 4;
    H4 im = ldH4(g_imgh, idx);
    H4 a0 = ldH4(q0, idx);
    H4 a1 = ldH4(q1, idx);
    H4 a2 = ldH4(q2, idx);
    dlo = __hsub2(__hsub2(__hsub2(im.lo, a0.lo), a1.lo), a2.lo);
    dhi = __hsub2(__hsub2(__hsub2(im.hi, a0.hi), a1.hi), a2.hi);
    if (b > 0) {
        H4 nb = ldH4(q0, idx - SB);
        dlo = __hadd2(dlo, nb.lo); dhi = __hadd2(dhi, nb.hi);
    }
    if (use_carry) {
        dlo = __hadd2(dlo, a1clo); dhi = __hadd2(dhi, a1chi);
    } else if (t > 0) {
        H4 nt = ldH4(q1, idx - ST);
        dlo = __hadd2(dlo, nt.lo); dhi = __hadd2(dhi, nt.hi);
    }
    // + p2[f-1]: shift a2 right one element across the warp row.
    unsigned prevw = __shfl_up_sync(0xffffffffu, h2u(a2.hi), 1);
    __half pe3 = (lane > 0)
        ? __ushort_as_half((unsigned short)(prevw >> 16)) : zeroh;
    __half2 shlo = __halves2half2(pe3, __low2half(a2.lo));
    __half2 shhi = __halves2half2(__high2half(a2.lo), __low2half(a2.hi));
    dlo = __hadd2(dlo, shlo);
    dhi = __hadd2(dhi, shhi);
    a1clo = a1.lo;
    a1chi = a1.hi;
}

// ---------------------------------------------------------------------------
// k_fused: one Chambolle step, half2 SIMD, split-warp ownership.
// 16 warps; warp (b = w&7, half = w>>3) owns t-rows {2*half, 2*half+1};
// half==1 warps also compute the halo row t0+4 (registers only).
// Halo overhead 5/4 rows (vs 3/2 at TTILE=2).
// ---------------------------------------------------------------------------
template <bool A2B>
__global__ __launch_bounds__(NTFUSED, 4)
void k_fused(const float* __restrict__ lam) {
    const __half* __restrict__ q0 = A2B ? g_pa0 : g_pb0;
    const __half* __restrict__ q1 = A2B ? g_pa1 : g_pb1;
    const __half* __restrict__ q2 = A2B ? g_pa2 : g_pb2;
    __half* __restrict__ w0 = A2B ? g_pb0 : g_pa0;
    __half* __restrict__ w1 = A2B ? g_pb1 : g_pa1;
    __half* __restrict__ w2 = A2B ? g_pb2 : g_pa2;

    __shared__ uint2 s_out[BB][TTILE][32];              // rows 0..3: 8 KB

    const int warp = threadIdx.x >> 5;
    const int b = warp & 7;
    const int half_ = warp >> 3;
    const int lane = threadIdx.x & 31;                  // == f4 index
    const int t0 = blockIdx.x * TTILE;
    const int r0w = 2 * half_;                          // first owned trow

    const float twf = TAU_F / lam[0];
    const __half2 tw2 = __float2half2_rn(twf);
    const __half2 one2 = __float2half2_rn(1.0f);
    const __half2 ntau2 = __float2half2_rn(-TAU_F);
    const __half2 zero2 = __float2half2_rn(0.0f);

    __half2 olo[3], ohi[3];                             // 2 owned rows + halo
    olo[2] = zero2; ohi[2] = zero2;
    __half2 a1clo = zero2, a1chi = zero2;

    // Phase A: owned rows (t-1 term: first row loads global, second carries).
    out_row(q0, q1, q2, b, t0 + r0w, lane, false, a1clo, a1chi, olo[0], ohi[0]);
    out_row(q0, q1, q2, b, t0 + r0w + 1, lane, true, a1clo, a1chi, olo[1], ohi[1]);
    {
        uint2 u;
        u.x = h2u(olo[0]); u.y = h2u(ohi[0]);
        s_out[b][r0w][lane] = u;
        u.x = h2u(olo[1]); u.y = h2u(ohi[1]);
        s_out[b][r0w + 1][lane] = u;
    }
    // Halo row t0+4 (half==1 warps only, registers only). Warp-uniform guard.
    if (half_ == 1 && t0 + TTILE < TT) {
        out_row(q0, q1, q2, b, t0 + TTILE, lane, true, a1clo, a1chi,
                olo[2], ohi[2]);
    }
    __syncthreads();

    // Phase B: owned rows trow = r0w, r0w+1.
#pragma unroll
    for (int i = 0; i < 2; ++i) {
        int trow = r0w + i;
        int t = t0 + trow;
        int idx = b * SB + t * ST + lane * 4;
        __half2 lo = olo[i], hi = ohi[i];

        __half2 gblo = zero2, gbhi = zero2;
        if (b < BB - 1) {                               // cross-b via smem
            uint2 nu = s_out[b + 1][trow][lane];
            gblo = __hsub2(u2h(nu.x), lo);
            gbhi = __hsub2(u2h(nu.y), hi);
        }
        __half2 gtlo = zero2, gthi = zero2;
        if (t < TT - 1) {
            __half2 nlo, nhi;
            if (i == 0) {                               // next owned row (regs)
                nlo = olo[1]; nhi = ohi[1];
            } else if (half_ == 0) {                    // row 2 via smem
                uint2 nu = s_out[b][2][lane];
                nlo = u2h(nu.x); nhi = u2h(nu.y);
            } else {                                    // halo row 4 (regs)
                nlo = olo[2]; nhi = ohi[2];
            }
            gtlo = __hsub2(nlo, lo);
            gthi = __hsub2(nhi, hi);
        }
        // gf: out shifted left one element; last element (f==127) -> 0.
        unsigned nextw = __shfl_down_sync(0xffffffffu, h2u(lo), 1);
        __half ne0 = (lane < 31)
            ? __ushort_as_half((unsigned short)(nextw & 0xffff))
            : __high2half(hi);                          // makes gf.w == 0
        __half2 sllo = __halves2half2(__high2half(lo), __low2half(hi));
        __half2 slhi = __halves2half2(__high2half(hi), ne0);
        __half2 gflo = __hsub2(sllo, lo);
        __half2 gfhi = __hsub2(slhi, hi);

        __half2 n2lo = __hfma2(gblo, gblo,
                        __hfma2(gtlo, gtlo, __hmul2(gflo, gflo)));
        __half2 n2hi = __hfma2(gbhi, gbhi,
                        __hfma2(gthi, gthi, __hmul2(gfhi, gfhi)));
        __half2 invlo = h2rcp(__hfma2(h2sqrt(n2lo), tw2, one2));
        __half2 invhi = h2rcp(__hfma2(h2sqrt(n2hi), tw2, one2));

        H4 a0 = ldH4(q0, idx);                          // L1 hits (Phase A)
        H4 a1 = ldH4(q1, idx);
        H4 a2 = ldH4(q2, idx);
        H4 o0, o1, o2;
        o0.lo = __hmul2(__hfma2(gblo, ntau2, a0.lo), invlo);
        o0.hi = __hmul2(__hfma2(gbhi, ntau2, a0.hi), invhi);
        o1.lo = __hmul2(__hfma2(gtlo, ntau2, a1.lo), invlo);
        o1.hi = __hmul2(__hfma2(gthi, ntau2, a1.hi), invhi);
        o2.lo = __hmul2(__hfma2(gflo, ntau2, a2.lo), invlo);
        o2.hi = __hmul2(__hfma2(gfhi, ntau2, a2.hi), invhi);
        stH4(w0, idx, o0);
        stH4(w1, idx, o1);
        stH4(w2, idx, o2);
    }
}

// ---------------------------------------------------------------------------
// k_final: out = img + div(pA) + bias[f]. fp32 math.
// ---------------------------------------------------------------------------
__global__ __launch_bounds__(NTHREADS)
void k_final(const float* __restrict__ img, const float* __restrict__ bias,
             float* __restrict__ out) {
    int tid = blockIdx.x * blockDim.x + threadIdx.x;
    if (tid >= NN / 4) return;
    int lane = tid & 31;
    int t = (tid >> 5) & (TT - 1);
    int b = tid >> 16;
    int idx = tid * 4;

    float4 d = ld4(img, idx);
    float4 a0 = ldh4(g_pa0, idx);
    float4 a1 = ldh4(g_pa1, idx);
    float4 a2 = ldh4(g_pa2, idx);
    d = f4sub(f4sub(f4sub(d, a0), a1), a2);
    if (b > 0) d = f4add(d, ldh4(g_pa0, idx - SB));
    if (t > 0) d = f4add(d, ldh4(g_pa1, idx - ST));
    float prevw = __shfl_up_sync(0xffffffffu, a2.w, 1);
    if (lane > 0) d.x += prevw;
    d.y += a2.x; d.z += a2.y; d.w += a2.z;

    d = f4add(d, ld4(bias, lane * 4));
    st4(out, idx, d);
}

extern "C" void kernel_launch(void* const* d_in, const int* in_sizes, int n_in,
                              void* d_out, int out_size) {
    const float* x   = (const float*)d_in[0];   // (8, 2048, 128)
    const float* lam = (const float*)d_in[1];   // (1, 1)
    const float* b   = (const float*)d_in[2];   // (1, 1, 128)
    float* out = (float*)d_out;

    const int vblocks = (NN / 4 + NTHREADS - 1) / NTHREADS;   // 2048
    const int fblocks = TT / TTILE;                           // 512

    k_first<<<vblocks, NTHREADS>>>(x, lam);

    for (int it = 0; it < NFUSED; ++it) {
        if ((it & 1) == 0)
            k_fused<true><<<fblocks, NTFUSED>>>(lam);   // A -> B
        else
            k_fused<false><<<fblocks, NTFUSED>>>(lam);  // B -> A
    }

    k_final<<<vblocks, NTHREADS>>>(x, b, out);
}